// round 13
// baseline (speedup 1.0000x reference)
#include <cuda_runtime.h>

#define NBATCH 4096
#define TT     2048
#define SDIM   5
#define CHUNK  16                // delta steps staged per smem refill
#define NCHUNK (TT / CHUNK)

typedef unsigned long long ull;

// ---- packed f32x2 helpers (sm_100+/sm_103a) ----
__device__ __forceinline__ ull pack2(float lo, float hi) {
    ull r; asm("mov.b64 %0, {%1, %2};" : "=l"(r) : "f"(lo), "f"(hi)); return r;
}
__device__ __forceinline__ float sum2(ull a) {
    float lo, hi; asm("mov.b64 {%0, %1}, %2;" : "=f"(lo), "=f"(hi) : "l"(a));
    return lo + hi;
}
__device__ __forceinline__ ull mul2(ull a, ull b) {
    ull d; asm("mul.rn.f32x2 %0, %1, %2;" : "=l"(d) : "l"(a), "l"(b)); return d;
}
__device__ __forceinline__ ull add2(ull a, ull b) {
    ull d; asm("add.rn.f32x2 %0, %1, %2;" : "=l"(d) : "l"(a), "l"(b)); return d;
}
__device__ __forceinline__ void fma2(ull& d, ull a, ull b) {
    asm("fma.rn.f32x2 %0, %1, %2, %0;" : "+l"(d) : "l"(a), "l"(b));
}

#define SC 2.885390081777926815f   // 2*log2(e): folded into W2/b2 only

__device__ __forceinline__ float tanh_hw(float x) {       // stage-1 (MUFU.TANH)
    float y; asm("tanh.approx.f32 %0, %1;" : "=f"(y) : "f"(x));
    return y;
}
__device__ __forceinline__ float tanh_pre(float y) {      // stage-2 (precise, prescaled)
    float e, r;
    asm("ex2.approx.f32 %0, %1;" : "=f"(e) : "f"(y));
    asm("rcp.approx.f32 %0, %1;" : "=f"(r) : "f"(e + 1.0f));
    return fmaf(-2.0f, r, 1.0f);
}

__global__ __launch_bounds__(32)   // 1 warp per block; regs effectively uncapped
void msc_seq_kernel(const float* __restrict__ delta,
                    const float* __restrict__ state0,
                    const float* __restrict__ W1, const float* __restrict__ b1,
                    const float* __restrict__ W2, const float* __restrict__ b2,
                    const float* __restrict__ W3, const float* __restrict__ b3,
                    float* __restrict__ out)
{
    // exchange lines: [seq][half][48]; halves 192B apart -> +16 banks, conflict-free
    __shared__ __align__(16) float sh1[2][2][48];     // h1
    __shared__ __align__(16) float sh2[2][2][48];     // h2
    __shared__ __align__(16) float shd[2][2][80];     // staged delta (float4/step)

    const int lane = threadIdx.x;        // 32-thread block = one warp
    const int h    = lane >> 4;          // which half (batch group)
    const int hl   = lane & 15;          // lane within half
    const int bA   = blockIdx.x * 4 + h * 2;   // two interleaved batches per half
    const int bB   = bA + 1;

    const int j0 = 2 * hl, j1 = 2 * hl + 1;    // ADJACENT owned channels -> STS.64
    const int ko = (hl < SDIM) ? hl : 4;       // output channel tracked by this lane
    const bool wrO = (hl < SDIM);

    // ---- W1 rows (state part for carry/M, delta part for stage 1) ----
    float w1sa[5], w1sc[5];
#pragma unroll
    for (int k = 0; k < 5; k++) {
        w1sa[k] = W1[k * 32 + j0];
        w1sc[k] = W1[k * 32 + j1];
    }
    float w1da[3], w1dc[3];
#pragma unroll
    for (int i = 0; i < 3; i++) {
        w1da[i] = W1[(5 + i) * 32 + j0];
        w1dc[i] = W1[(5 + i) * 32 + j1];
    }

    // ---- packed per-lane weight blocks ----
    // w2p/w2q: W2 columns j0/j1 (prescaled for tanh_pre)
    // mpa/mpc: M columns j0/j1, M[i][j] = sum_k W3[i][k] * W1[k][j]  (carry update)
    // w3o:     W3 column ko (this lane's output channel)
    ull w2p[16], w2q[16], mpa[16], mpc[16], w3o[16];
#pragma unroll
    for (int p = 0; p < 16; p++) {
        const int i0 = 2 * p, i1 = 2 * p + 1;
        w2p[p] = pack2(W2[i0 * 32 + j0] * SC, W2[i1 * 32 + j0] * SC);
        w2q[p] = pack2(W2[i0 * 32 + j1] * SC, W2[i1 * 32 + j1] * SC);
        float m0a = 0.f, m1a = 0.f, m0c = 0.f, m1c = 0.f;
#pragma unroll
        for (int k = 0; k < 5; k++) {
            m0a = fmaf(W3[i0 * SDIM + k], w1sa[k], m0a);
            m1a = fmaf(W3[i1 * SDIM + k], w1sa[k], m1a);
            m0c = fmaf(W3[i0 * SDIM + k], w1sc[k], m0c);
            m1c = fmaf(W3[i1 * SDIM + k], w1sc[k], m1c);
        }
        mpa[p] = pack2(m0a, m1a);
        mpc[p] = pack2(m0c, m1c);
        w3o[p] = pack2(W3[i0 * SDIM + ko], W3[i1 * SDIM + ko]);
    }

    // g_j = (W1_s^T b3)_j  -- constant added to carry each step
    float ga = 0.f, gc = 0.f;
#pragma unroll
    for (int k = 0; k < 5; k++) {
        ga = fmaf(b3[k], w1sa[k], ga);
        gc = fmaf(b3[k], w1sc[k], gc);
    }
    const float b2a = b2[j0] * SC, b2c = b2[j1] * SC;
    const float b3k = b3[ko];

    // ---- carries: cb_j = b1_j + (W1_s^T s)_j ; per seq, per owned channel ----
    float cbAa = b1[j0], cbAc = b1[j1], cbBa = b1[j0], cbBc = b1[j1];
#pragma unroll
    for (int k = 0; k < 5; k++) {
        const float sA = state0[bA * SDIM + k];
        const float sB = state0[bB * SDIM + k];
        cbAa = fmaf(sA, w1sa[k], cbAa);
        cbAc = fmaf(sA, w1sc[k], cbAc);
        cbBa = fmaf(sB, w1sa[k], cbBa);
        cbBc = fmaf(sB, w1sc[k], cbBc);
    }
    float stkA = state0[bA * SDIM + ko];     // this lane's output channel value
    float stkB = state0[bB * SDIM + ko];

    const float* dApt = delta + (size_t)bA * (TT * 3);
    const float* dBpt = delta + (size_t)bB * (TT * 3);
    float* oA = out + (size_t)bA * (TT * SDIM) + ko;
    float* oB = out + (size_t)bB * (TT * SDIM) + ko;

    float rA0 = dApt[hl * 3 + 0], rA1 = dApt[hl * 3 + 1], rA2 = dApt[hl * 3 + 2];
    float rB0 = dBpt[hl * 3 + 0], rB1 = dBpt[hl * 3 + 1], rB2 = dBpt[hl * 3 + 2];

    float* l1A = &sh1[0][h][0];
    float* l1B = &sh1[1][h][0];
    float* l2A = &sh2[0][h][0];
    float* l2B = &sh2[1][h][0];

    // ---- per-seq phases (no cross-lane shuffles anywhere) ----
    auto stage1 = [&](float cba, float cbc, const float4 dv, float* line) {
        float aa = cba;
        aa = fmaf(dv.x, w1da[0], aa);
        aa = fmaf(dv.y, w1da[1], aa);
        aa = fmaf(dv.z, w1da[2], aa);
        float ac = cbc;
        ac = fmaf(dv.x, w1dc[0], ac);
        ac = fmaf(dv.y, w1dc[1], ac);
        ac = fmaf(dv.z, w1dc[2], ac);
        *(float2*)(&line[j0]) = make_float2(tanh_hw(aa), tanh_hw(ac));
    };

    auto stage2 = [&](const float* line1, float* line2) {
        const ulonglong2* hp = (const ulonglong2*)line1;
        ulonglong2 u = hp[0];
        ull a0 = mul2(u.x, w2p[0]);
        ull a1 = mul2(u.y, w2p[1]);
        ull c0 = mul2(u.x, w2q[0]);
        ull c1 = mul2(u.y, w2q[1]);
#pragma unroll
        for (int p = 1; p < 8; p++) {
            u = hp[p];
            fma2(a0, u.x, w2p[2 * p]);
            fma2(a1, u.y, w2p[2 * p + 1]);
            fma2(c0, u.x, w2q[2 * p]);
            fma2(c1, u.y, w2q[2 * p + 1]);
        }
        const float h2a = tanh_pre(sum2(add2(a0, a1)) + b2a);
        const float h2c = tanh_pre(sum2(add2(c0, c1)) + b2c);
        *(float2*)(&line2[j0]) = make_float2(h2a, h2c);
    };

    auto stage3 = [&](const float* line2, float& cba, float& cbc, float& stk,
                      float* op) {
        const ulonglong2* hp = (const ulonglong2*)line2;
        ulonglong2 u = hp[0];
        ull ma0 = mul2(u.x, mpa[0]);
        ull ma1 = mul2(u.y, mpa[1]);
        ull mc0 = mul2(u.x, mpc[0]);
        ull mc1 = mul2(u.y, mpc[1]);
        ull oo0 = mul2(u.x, w3o[0]);
        ull oo1 = mul2(u.y, w3o[1]);
#pragma unroll
        for (int p = 1; p < 8; p++) {
            u = hp[p];
            fma2(ma0, u.x, mpa[2 * p]);
            fma2(ma1, u.y, mpa[2 * p + 1]);
            fma2(mc0, u.x, mpc[2 * p]);
            fma2(mc1, u.y, mpc[2 * p + 1]);
            fma2(oo0, u.x, w3o[2 * p]);
            fma2(oo1, u.y, w3o[2 * p + 1]);
        }
        cba += ga + sum2(add2(ma0, ma1));    // carry update (exact reformulation)
        cbc += gc + sum2(add2(mc0, mc1));
        stk += b3k + sum2(add2(oo0, oo1));   // this lane's output channel
        if (wrO) *op = stk;
    };

    for (int c = 0; c < NCHUNK; c++) {
        __syncwarp();
        *(float4*)(&shd[0][h][hl * 4]) = make_float4(rA0, rA1, rA2, 0.f);
        *(float4*)(&shd[1][h][hl * 4]) = make_float4(rB0, rB1, rB2, 0.f);
        __syncwarp();
        if (c + 1 < NCHUNK) {
            const float* nA = dApt + (size_t)(c + 1) * (CHUNK * 3);
            const float* nB = dBpt + (size_t)(c + 1) * (CHUNK * 3);
            rA0 = nA[hl * 3 + 0]; rA1 = nA[hl * 3 + 1]; rA2 = nA[hl * 3 + 2];
            rB0 = nB[hl * 3 + 0]; rB1 = nB[hl * 3 + 1]; rB2 = nB[hl * 3 + 2];
        }

#pragma unroll 1
        for (int tl = 0; tl < CHUNK; tl++) {
            const float4 dvA = *(const float4*)(&shd[0][h][tl * 4]);
            const float4 dvB = *(const float4*)(&shd[1][h][tl * 4]);

            stage1(cbAa, cbAc, dvA, l1A);
            stage1(cbBa, cbBc, dvB, l1B);
            __syncwarp();                    // h1 visible

            stage2(l1A, l2A);
            stage2(l1B, l2B);
            __syncwarp();                    // h2 visible (also protects h1 reuse)

            stage3(l2A, cbAa, cbAc, stkA, oA);
            stage3(l2B, cbBa, cbBc, stkB, oB);
            oA += SDIM;
            oB += SDIM;
        }
    }
}

extern "C" void kernel_launch(void* const* d_in, const int* in_sizes, int n_in,
                              void* d_out, int out_size)
{
    const float* delta  = (const float*)d_in[0];
    const float* state0 = (const float*)d_in[1];
    const float* W1     = (const float*)d_in[2];
    const float* b1     = (const float*)d_in[3];
    const float* W2     = (const float*)d_in[4];
    const float* b2     = (const float*)d_in[5];
    const float* W3     = (const float*)d_in[6];
    const float* b3     = (const float*)d_in[7];
    float* out = (float*)d_out;

    dim3 grid(NBATCH / 4);   // 1024 one-warp blocks, 4 batches each
    dim3 block(32);
    msc_seq_kernel<<<grid, block>>>(delta, state0, W1, b1, W2, b2, W3, b3, out);
}

// round 14
// speedup vs baseline: 1.5927x; 1.5927x over previous
#include <cuda_runtime.h>

#define NBATCH 4096
#define TT     2048
#define SDIM   5
#define CHUNK  8                 // delta steps staged per smem refill
#define NCHUNK (TT / CHUNK)

typedef unsigned long long ull;

// ---- packed f32x2 helpers (sm_100+/sm_103a) ----
__device__ __forceinline__ ull pack2(float lo, float hi) {
    ull r; asm("mov.b64 %0, {%1, %2};" : "=l"(r) : "f"(lo), "f"(hi)); return r;
}
__device__ __forceinline__ float sum2(ull a) {
    float lo, hi; asm("mov.b64 {%0, %1}, %2;" : "=f"(lo), "=f"(hi) : "l"(a));
    return lo + hi;
}
__device__ __forceinline__ ull mul2(ull a, ull b) {
    ull d; asm("mul.rn.f32x2 %0, %1, %2;" : "=l"(d) : "l"(a), "l"(b)); return d;
}
__device__ __forceinline__ ull add2(ull a, ull b) {
    ull d; asm("add.rn.f32x2 %0, %1, %2;" : "=l"(d) : "l"(a), "l"(b)); return d;
}
__device__ __forceinline__ void fma2(ull& d, ull a, ull b) {
    asm("fma.rn.f32x2 %0, %1, %2, %0;" : "+l"(d) : "l"(a), "l"(b));
}

#define SC 2.885390081777926815f   // 2*log2(e): folded into W2/b2 only

__device__ __forceinline__ float tanh_hw(float x) {       // stage-1 (MUFU.TANH)
    float y; asm("tanh.approx.f32 %0, %1;" : "=f"(y) : "f"(x));
    return y;
}
__device__ __forceinline__ float tanh_pre(float y) {      // stage-2 (precise, prescaled)
    float e, r;
    asm("ex2.approx.f32 %0, %1;" : "=f"(e) : "f"(y));
    asm("rcp.approx.f32 %0, %1;" : "=f"(r) : "f"(e + 1.0f));
    return fmaf(-2.0f, r, 1.0f);
}

#define SHF8(v, src) __shfl_sync(0xffffffffu, (v), (src), 8)
#define SHFX(v, m)   __shfl_xor_sync(0xffffffffu, (v), (m))

__global__ __launch_bounds__(32)   // 1 warp per block; regs effectively uncapped
void msc_seq_kernel(const float* __restrict__ delta,
                    const float* __restrict__ state0,
                    const float* __restrict__ W1, const float* __restrict__ b1,
                    const float* __restrict__ W2, const float* __restrict__ b2,
                    const float* __restrict__ W3, const float* __restrict__ b3,
                    float* __restrict__ out)
{
    // per-quarter lines, stride 40 floats (160B) -> quarter bases at banks 0/8/16/24
    __shared__ __align__(16) float sh1[4][40];   // h1 exchange
    __shared__ __align__(16) float shd[4][40];   // staged delta (float4 per step)

    const int lane = threadIdx.x;        // 32-thread block = one warp
    const int q    = lane >> 3;          // quarter (batch) 0..3
    const int ql   = lane & 7;           // lane within quarter
    const int b    = blockIdx.x * 4 + q; // this quarter's batch element

    const int jb = 4 * ql;               // 4 ADJACENT owned channels -> STS.128

    // ---- weights in registers ----
    float w1r[4][8];                     // UNSCALED (stage-1 uses tanh.approx)
#pragma unroll
    for (int cc = 0; cc < 4; cc++)
#pragma unroll
        for (int i = 0; i < 8; i++)
            w1r[cc][i] = W1[i * 32 + jb + cc];

    ull w2c[4][16];                      // W2 columns jb..jb+3, packed+prescaled
#pragma unroll
    for (int cc = 0; cc < 4; cc++)
#pragma unroll
        for (int p = 0; p < 16; p++)
            w2c[cc][p] = pack2(W2[(2 * p) * 32 + jb + cc] * SC,
                               W2[(2 * p + 1) * 32 + jb + cc] * SC);

    float w3r[4][5];                     // W3 rows (UNscaled, feeds residual state)
#pragma unroll
    for (int cc = 0; cc < 4; cc++)
#pragma unroll
        for (int k = 0; k < 5; k++)
            w3r[cc][k] = W3[(jb + cc) * SDIM + k];

    float b1r[4], b2r[4];
#pragma unroll
    for (int cc = 0; cc < 4; cc++) {
        b1r[cc] = b1[jb + cc];
        b2r[cc] = b2[jb + cc] * SC;
    }

    // ---- slot mapping (8-lane merge tree: xor4, xor2, xor1) ----
    const int t2 = (ql >> 2) & 1, t1 = (ql >> 1) & 1, t0 = ql & 1;
    const int vidx = t0 ? 4 : (t1 ? (t2 ? 3 : 2) : (t2 ? 1 : 0));
    // slot lanes per quarter: ch0<-0, ch1<-4, ch2<-2, ch3<-6, ch4<-1
    const bool wr = (ql == 0) | (ql == 1) | (ql == 2) | (ql == 4) | (ql == 6);
    const float b3v = b3[vidx];

    float stv = state0[b * SDIM + vidx]; // lane carries its slot's state channel

    const float* dptr = delta + (size_t)b * (TT * 3);
    float*       optr = out   + (size_t)b * (TT * SDIM) + vidx;

    float* line = &sh1[q][0];
    const ulonglong2* hp = (const ulonglong2*)line;

    // prefetch first delta chunk: lane (q,ql) holds step ql of batch b
    float r0 = dptr[ql * 3 + 0];
    float r1 = dptr[ql * 3 + 1];
    float r2 = dptr[ql * 3 + 2];

    for (int c = 0; c < NCHUNK; c++) {
        __syncwarp();                    // prior chunk's delta reads done
        *(float4*)(&shd[q][ql * 4]) = make_float4(r0, r1, r2, 0.f);
        __syncwarp();
        if (c + 1 < NCHUNK) {
            const float* np = dptr + (size_t)(c + 1) * (CHUNK * 3);
            r0 = np[ql * 3 + 0];
            r1 = np[ql * 3 + 1];
            r2 = np[ql * 3 + 2];
        }

#pragma unroll 2
        for (int tl = 0; tl < CHUNK; tl++) {
            const float4 dv = *(const float4*)(&shd[q][tl * 4]);

            // ---- broadcast state channels within the quarter (width=8 shfl) ----
            const float s0 = SHF8(stv, 0);
            const float s1 = SHF8(stv, 4);
            const float s2 = SHF8(stv, 2);
            const float s3 = SHF8(stv, 6);
            const float s4 = SHF8(stv, 1);

            // ---- stage 1: h1 for 4 owned channels ----
            float h1v[4];
#pragma unroll
            for (int cc = 0; cc < 4; cc++) {
                float a = b1r[cc];
                a = fmaf(dv.x, w1r[cc][5], a);
                a = fmaf(dv.y, w1r[cc][6], a);
                a = fmaf(dv.z, w1r[cc][7], a);
                a = fmaf(s0, w1r[cc][0], a);
                a = fmaf(s1, w1r[cc][1], a);
                a = fmaf(s2, w1r[cc][2], a);
                a = fmaf(s3, w1r[cc][3], a);
                a = fmaf(s4, w1r[cc][4], a);
                h1v[cc] = tanh_hw(a);
            }
            // 4 adjacent channels -> single STS.128
            *(float4*)(&line[jb]) = make_float4(h1v[0], h1v[1], h1v[2], h1v[3]);
            __syncwarp();

            // ---- stage 2: 4 channels, 2 packed chains each (8 LDS.128 total) ----
            ull a0[4], a1[4];
            ulonglong2 u = hp[0];
#pragma unroll
            for (int cc = 0; cc < 4; cc++) {
                a0[cc] = mul2(u.x, w2c[cc][0]);
                a1[cc] = mul2(u.y, w2c[cc][1]);
            }
#pragma unroll
            for (int p = 1; p < 8; p++) {
                u = hp[p];
#pragma unroll
                for (int cc = 0; cc < 4; cc++) {
                    fma2(a0[cc], u.x, w2c[cc][2 * p]);
                    fma2(a1[cc], u.y, w2c[cc][2 * p + 1]);
                }
            }
            float h2v[4];
#pragma unroll
            for (int cc = 0; cc < 4; cc++)
                h2v[cc] = tanh_pre(sum2(add2(a0[cc], a1[cc])) + b2r[cc]);

            // ---- stage 3: products (4ch -> 5 outputs), 8-lane slot-merge tree ----
            float pr[5];
#pragma unroll
            for (int k = 0; k < 5; k++) {
                float p = h2v[0] * w3r[0][k];
                p = fmaf(h2v[1], w3r[1][k], p);
                p = fmaf(h2v[2], w3r[2][k], p);
                p = fmaf(h2v[3], w3r[3][k], p);
                pr[k] = p;
            }

            // r1 (xor 4): (p0,p1)->A, (p2,p3)->B, p4 butterfly
            float A  = t2 ? pr[1] : pr[0];
            float Au = t2 ? pr[0] : pr[1];
            A += SHFX(Au, 4);
            float Bt = t2 ? pr[3] : pr[2];
            float Bu = t2 ? pr[2] : pr[3];
            Bt += SHFX(Bu, 4);
            float p4 = pr[4] + SHFX(pr[4], 4);
            // r2 (xor 2): (A,B)->C, p4 butterfly
            float Ct = t1 ? Bt : A;
            float Cu = t1 ? A : Bt;
            Ct += SHFX(Cu, 2);
            p4 += SHFX(p4, 2);
            // r3 (xor 1): (C,p4)->D
            float D  = t0 ? p4 : Ct;
            float Du = t0 ? Ct : p4;
            D += SHFX(Du, 1);

            stv += D + b3v;              // every lane updates its slot channel

            if (wr) *optr = stv;         // lanes {0,4,2,6,1} -> channels {0..4}
            optr += SDIM;
        }
    }
}

extern "C" void kernel_launch(void* const* d_in, const int* in_sizes, int n_in,
                              void* d_out, int out_size)
{
    const float* delta  = (const float*)d_in[0];
    const float* state0 = (const float*)d_in[1];
    const float* W1     = (const float*)d_in[2];
    const float* b1     = (const float*)d_in[3];
    const float* W2     = (const float*)d_in[4];
    const float* b2     = (const float*)d_in[5];
    const float* W3     = (const float*)d_in[6];
    const float* b3     = (const float*)d_in[7];
    float* out = (float*)d_out;

    dim3 grid(NBATCH / 4);   // 1024 one-warp blocks, 4 batches each (8 lanes/batch)
    dim3 block(32);
    msc_seq_kernel<<<grid, block>>>(delta, state0, W1, b1, W2, b2, W3, b3, out);
}

// round 15
// speedup vs baseline: 1.6069x; 1.0090x over previous
#include <cuda_runtime.h>

#define NBATCH 4096
#define TT     2048
#define SDIM   5
#define CHUNK  8                 // delta steps staged per smem refill
#define NCHUNK (TT / CHUNK)

typedef unsigned long long ull;

// ---- packed f32x2 helpers (sm_100+/sm_103a) ----
__device__ __forceinline__ ull pack2(float lo, float hi) {
    ull r; asm("mov.b64 %0, {%1, %2};" : "=l"(r) : "f"(lo), "f"(hi)); return r;
}
__device__ __forceinline__ void unpack2(ull a, float& lo, float& hi) {
    asm("mov.b64 {%0, %1}, %2;" : "=f"(lo), "=f"(hi) : "l"(a));
}
__device__ __forceinline__ float sum2(ull a) {
    float lo, hi; asm("mov.b64 {%0, %1}, %2;" : "=f"(lo), "=f"(hi) : "l"(a));
    return lo + hi;
}
__device__ __forceinline__ ull dup2(float v) {          // (v, v)
    ull r; asm("mov.b64 %0, {%1, %1};" : "=l"(r) : "f"(v)); return r;
}
__device__ __forceinline__ ull mul2(ull a, ull b) {
    ull d; asm("mul.rn.f32x2 %0, %1, %2;" : "=l"(d) : "l"(a), "l"(b)); return d;
}
__device__ __forceinline__ ull add2(ull a, ull b) {
    ull d; asm("add.rn.f32x2 %0, %1, %2;" : "=l"(d) : "l"(a), "l"(b)); return d;
}
__device__ __forceinline__ void fma2(ull& d, ull a, ull b) {
    asm("fma.rn.f32x2 %0, %1, %2, %0;" : "+l"(d) : "l"(a), "l"(b));
}

#define SC 2.885390081777926815f   // 2*log2(e): folded into W2/b2 only

__device__ __forceinline__ float tanh_hw(float x) {       // stage-1 (MUFU.TANH)
    float y; asm("tanh.approx.f32 %0, %1;" : "=f"(y) : "f"(x));
    return y;
}
__device__ __forceinline__ float tanh_pre(float y) {      // stage-2 (precise, prescaled)
    float e, r;
    asm("ex2.approx.f32 %0, %1;" : "=f"(e) : "f"(y));
    asm("rcp.approx.f32 %0, %1;" : "=f"(r) : "f"(e + 1.0f));
    return fmaf(-2.0f, r, 1.0f);
}

#define SHF8(v, src) __shfl_sync(0xffffffffu, (v), (src), 8)
#define SHFX(v, m)   __shfl_xor_sync(0xffffffffu, (v), (m))

__global__ __launch_bounds__(32)   // 1 warp per block; regs effectively uncapped
void msc_seq_kernel(const float* __restrict__ delta,
                    const float* __restrict__ state0,
                    const float* __restrict__ W1, const float* __restrict__ b1,
                    const float* __restrict__ W2, const float* __restrict__ b2,
                    const float* __restrict__ W3, const float* __restrict__ b3,
                    float* __restrict__ out)
{
    // per-quarter lines, stride 40 floats (160B) -> quarter bases at banks 0/8/16/24
    __shared__ __align__(16) float sh1[4][40];   // h1 exchange
    __shared__ __align__(16) float shd[4][40];   // staged delta (float4 per step)

    const int lane = threadIdx.x;        // 32-thread block = one warp
    const int q    = lane >> 3;          // quarter (batch) 0..3
    const int ql   = lane & 7;           // lane within quarter
    const int b    = blockIdx.x * 4 + q; // this quarter's batch element

    const int jb = 4 * ql;               // 4 ADJACENT owned channels -> STS.128

    // ---- weights in registers ----
    // stage-1 W1 packed by channel pair: w1p01[i] = (W1[i][jb], W1[i][jb+1]),
    //                                    w1p23[i] = (W1[i][jb+2], W1[i][jb+3])
    ull w1p01[8], w1p23[8];              // UNSCALED (stage-1 uses tanh.approx)
#pragma unroll
    for (int i = 0; i < 8; i++) {
        w1p01[i] = pack2(W1[i * 32 + jb + 0], W1[i * 32 + jb + 1]);
        w1p23[i] = pack2(W1[i * 32 + jb + 2], W1[i * 32 + jb + 3]);
    }

    ull w2c[4][16];                      // W2 columns jb..jb+3, packed+prescaled
#pragma unroll
    for (int cc = 0; cc < 4; cc++)
#pragma unroll
        for (int p = 0; p < 16; p++)
            w2c[cc][p] = pack2(W2[(2 * p) * 32 + jb + cc] * SC,
                               W2[(2 * p + 1) * 32 + jb + cc] * SC);

    float w3r[4][5];                     // W3 rows (UNscaled, feeds residual state)
#pragma unroll
    for (int cc = 0; cc < 4; cc++)
#pragma unroll
        for (int k = 0; k < 5; k++)
            w3r[cc][k] = W3[(jb + cc) * SDIM + k];

    const ull b1p01 = pack2(b1[jb + 0], b1[jb + 1]);
    const ull b1p23 = pack2(b1[jb + 2], b1[jb + 3]);
    float b2r[4];
#pragma unroll
    for (int cc = 0; cc < 4; cc++)
        b2r[cc] = b2[jb + cc] * SC;

    // ---- slot mapping (8-lane merge tree: xor4, xor2, xor1) ----
    const int t2 = (ql >> 2) & 1, t1 = (ql >> 1) & 1, t0 = ql & 1;
    const int vidx = t0 ? 4 : (t1 ? (t2 ? 3 : 2) : (t2 ? 1 : 0));
    // slot lanes per quarter: ch0<-0, ch1<-4, ch2<-2, ch3<-6, ch4<-1
    const bool wr = (ql == 0) | (ql == 1) | (ql == 2) | (ql == 4) | (ql == 6);
    const float b3v = b3[vidx];

    float stv = state0[b * SDIM + vidx]; // lane carries its slot's state channel

    const float* dptr = delta + (size_t)b * (TT * 3);
    float*       optr = out   + (size_t)b * (TT * SDIM) + vidx;

    float* line = &sh1[q][0];
    const ulonglong2* hp = (const ulonglong2*)line;

    // prefetch first delta chunk: lane (q,ql) holds step ql of batch b
    float r0 = dptr[ql * 3 + 0];
    float r1 = dptr[ql * 3 + 1];
    float r2 = dptr[ql * 3 + 2];

    for (int c = 0; c < NCHUNK; c++) {
        __syncwarp();                    // prior chunk's delta reads done
        *(float4*)(&shd[q][ql * 4]) = make_float4(r0, r1, r2, 0.f);
        __syncwarp();
        if (c + 1 < NCHUNK) {
            const float* np = dptr + (size_t)(c + 1) * (CHUNK * 3);
            r0 = np[ql * 3 + 0];
            r1 = np[ql * 3 + 1];
            r2 = np[ql * 3 + 2];
        }

#pragma unroll 2
        for (int tl = 0; tl < CHUNK; tl++) {
            const float4 dv = *(const float4*)(&shd[q][tl * 4]);

            // ---- broadcast state channels within the quarter (width=8 shfl) ----
            const float s0 = SHF8(stv, 0);
            const float s1 = SHF8(stv, 4);
            const float s2 = SHF8(stv, 2);
            const float s3 = SHF8(stv, 6);
            const float s4 = SHF8(stv, 1);

            // ---- stage 1: packed f32x2 over channel pairs (16 fma2) ----
            const ull xd0 = dup2(dv.x);
            const ull xd1 = dup2(dv.y);
            const ull xd2 = dup2(dv.z);
            const ull xs0 = dup2(s0);
            const ull xs1 = dup2(s1);
            const ull xs2 = dup2(s2);
            const ull xs3 = dup2(s3);
            const ull xs4 = dup2(s4);

            ull acc01 = b1p01, acc23 = b1p23;
            fma2(acc01, xd0, w1p01[5]); fma2(acc23, xd0, w1p23[5]);
            fma2(acc01, xd1, w1p01[6]); fma2(acc23, xd1, w1p23[6]);
            fma2(acc01, xd2, w1p01[7]); fma2(acc23, xd2, w1p23[7]);
            fma2(acc01, xs0, w1p01[0]); fma2(acc23, xs0, w1p23[0]);
            fma2(acc01, xs1, w1p01[1]); fma2(acc23, xs1, w1p23[1]);
            fma2(acc01, xs2, w1p01[2]); fma2(acc23, xs2, w1p23[2]);
            fma2(acc01, xs3, w1p01[3]); fma2(acc23, xs3, w1p23[3]);
            fma2(acc01, xs4, w1p01[4]); fma2(acc23, xs4, w1p23[4]);

            float a0f, a1f, a2f, a3f;
            unpack2(acc01, a0f, a1f);
            unpack2(acc23, a2f, a3f);
            // 4 adjacent channels -> single STS.128
            *(float4*)(&line[jb]) = make_float4(tanh_hw(a0f), tanh_hw(a1f),
                                                tanh_hw(a2f), tanh_hw(a3f));
            __syncwarp();

            // ---- stage 2: 4 channels, 2 packed chains each (8 LDS.128 total) ----
            ull a0[4], a1[4];
            ulonglong2 u = hp[0];
#pragma unroll
            for (int cc = 0; cc < 4; cc++) {
                a0[cc] = mul2(u.x, w2c[cc][0]);
                a1[cc] = mul2(u.y, w2c[cc][1]);
            }
#pragma unroll
            for (int p = 1; p < 8; p++) {
                u = hp[p];
#pragma unroll
                for (int cc = 0; cc < 4; cc++) {
                    fma2(a0[cc], u.x, w2c[cc][2 * p]);
                    fma2(a1[cc], u.y, w2c[cc][2 * p + 1]);
                }
            }
            float h2v[4];
#pragma unroll
            for (int cc = 0; cc < 4; cc++)
                h2v[cc] = tanh_pre(sum2(add2(a0[cc], a1[cc])) + b2r[cc]);

            // ---- stage 3: products (4ch -> 5 outputs), 8-lane slot-merge tree ----
            float pr[5];
#pragma unroll
            for (int k = 0; k < 5; k++) {
                float p = h2v[0] * w3r[0][k];
                p = fmaf(h2v[1], w3r[1][k], p);
                p = fmaf(h2v[2], w3r[2][k], p);
                p = fmaf(h2v[3], w3r[3][k], p);
                pr[k] = p;
            }

            // r1 (xor 4): (p0,p1)->A, (p2,p3)->B, p4 butterfly
            float A  = t2 ? pr[1] : pr[0];
            float Au = t2 ? pr[0] : pr[1];
            A += SHFX(Au, 4);
            float Bt = t2 ? pr[3] : pr[2];
            float Bu = t2 ? pr[2] : pr[3];
            Bt += SHFX(Bu, 4);
            float p4 = pr[4] + SHFX(pr[4], 4);
            // r2 (xor 2): (A,B)->C, p4 butterfly
            float Ct = t1 ? Bt : A;
            float Cu = t1 ? A : Bt;
            Ct += SHFX(Cu, 2);
            p4 += SHFX(p4, 2);
            // r3 (xor 1): (C,p4)->D
            float D  = t0 ? p4 : Ct;
            float Du = t0 ? Ct : p4;
            D += SHFX(Du, 1);

            stv += D + b3v;              // every lane updates its slot channel

            if (wr) *optr = stv;         // lanes {0,4,2,6,1} -> channels {0..4}
            optr += SDIM;
        }
    }
}

extern "C" void kernel_launch(void* const* d_in, const int* in_sizes, int n_in,
                              void* d_out, int out_size)
{
    const float* delta  = (const float*)d_in[0];
    const float* state0 = (const float*)d_in[1];
    const float* W1     = (const float*)d_in[2];
    const float* b1     = (const float*)d_in[3];
    const float* W2     = (const float*)d_in[4];
    const float* b2     = (const float*)d_in[5];
    const float* W3     = (const float*)d_in[6];
    const float* b3     = (const float*)d_in[7];
    float* out = (float*)d_out;

    dim3 grid(NBATCH / 4);   // 1024 one-warp blocks, 4 batches each (8 lanes/batch)
    dim3 block(32);
    msc_seq_kernel<<<grid, block>>>(delta, state0, W1, b1, W2, b2, W3, b3, out);
}

// round 16
// speedup vs baseline: 1.6212x; 1.0089x over previous
#include <cuda_runtime.h>

#define NBATCH 4096
#define TT     2048
#define SDIM   5
#define CHUNK  8                 // delta steps staged per smem refill
#define NCHUNK (TT / CHUNK)

typedef unsigned long long ull;

// ---- packed f32x2 helpers (sm_100+/sm_103a) ----
__device__ __forceinline__ ull pack2(float lo, float hi) {
    ull r; asm("mov.b64 %0, {%1, %2};" : "=l"(r) : "f"(lo), "f"(hi)); return r;
}
__device__ __forceinline__ void unpack2(ull a, float& lo, float& hi) {
    asm("mov.b64 {%0, %1}, %2;" : "=f"(lo), "=f"(hi) : "l"(a));
}
__device__ __forceinline__ float sum2(ull a) {
    float lo, hi; asm("mov.b64 {%0, %1}, %2;" : "=f"(lo), "=f"(hi) : "l"(a));
    return lo + hi;
}
__device__ __forceinline__ ull dup2(float v) {          // (v, v)
    ull r; asm("mov.b64 %0, {%1, %1};" : "=l"(r) : "f"(v)); return r;
}
__device__ __forceinline__ ull mul2(ull a, ull b) {
    ull d; asm("mul.rn.f32x2 %0, %1, %2;" : "=l"(d) : "l"(a), "l"(b)); return d;
}
__device__ __forceinline__ ull add2(ull a, ull b) {
    ull d; asm("add.rn.f32x2 %0, %1, %2;" : "=l"(d) : "l"(a), "l"(b)); return d;
}
__device__ __forceinline__ void fma2(ull& d, ull a, ull b) {
    asm("fma.rn.f32x2 %0, %1, %2, %0;" : "+l"(d) : "l"(a), "l"(b));
}

#define SC 2.885390081777926815f   // 2*log2(e): folded into W2/b2 only

__device__ __forceinline__ float tanh_hw(float x) {       // stage-1 (MUFU.TANH)
    float y; asm("tanh.approx.f32 %0, %1;" : "=f"(y) : "f"(x));
    return y;
}
__device__ __forceinline__ float tanh_pre(float y) {      // stage-2 (precise, prescaled)
    float e, r;
    asm("ex2.approx.f32 %0, %1;" : "=f"(e) : "f"(y));
    asm("rcp.approx.f32 %0, %1;" : "=f"(r) : "f"(e + 1.0f));
    return fmaf(-2.0f, r, 1.0f);
}

#define SHF8(v, src) __shfl_sync(0xffffffffu, (v), (src), 8)

__global__ __launch_bounds__(32)   // 1 warp per block; regs effectively uncapped
void msc_seq_kernel(const float* __restrict__ delta,
                    const float* __restrict__ state0,
                    const float* __restrict__ W1, const float* __restrict__ b1,
                    const float* __restrict__ W2, const float* __restrict__ b2,
                    const float* __restrict__ W3, const float* __restrict__ b3,
                    float* __restrict__ out)
{
    // per-quarter lines, stride 40 floats (160B) -> quarter bases at banks 0/8/16/24
    __shared__ __align__(16) float sh1[4][40];   // h1 exchange, REUSED for h2
    __shared__ __align__(16) float shd[4][40];   // staged delta (float4 per step)

    const int lane = threadIdx.x;        // 32-thread block = one warp
    const int q    = lane >> 3;          // quarter (batch) 0..3
    const int ql   = lane & 7;           // lane within quarter
    const int b    = blockIdx.x * 4 + q; // this quarter's batch element

    const int jb = 4 * ql;               // 4 ADJACENT owned channels -> STS.128

    // ---- weights in registers ----
    // stage-1 W1 packed by channel pair
    ull w1p01[8], w1p23[8];              // UNSCALED (stage-1 uses tanh.approx)
#pragma unroll
    for (int i = 0; i < 8; i++) {
        w1p01[i] = pack2(W1[i * 32 + jb + 0], W1[i * 32 + jb + 1]);
        w1p23[i] = pack2(W1[i * 32 + jb + 2], W1[i * 32 + jb + 3]);
    }

    ull w2c[4][16];                      // W2 columns jb..jb+3, packed+prescaled
#pragma unroll
    for (int cc = 0; cc < 4; cc++)
#pragma unroll
        for (int p = 0; p < 16; p++)
            w2c[cc][p] = pack2(W2[(2 * p) * 32 + jb + cc] * SC,
                               W2[(2 * p + 1) * 32 + jb + cc] * SC);

    const ull b1p01 = pack2(b1[jb + 0], b1[jb + 1]);
    const ull b1p23 = pack2(b1[jb + 2], b1[jb + 3]);
    float b2r[4];
#pragma unroll
    for (int cc = 0; cc < 4; cc++)
        b2r[cc] = b2[jb + cc] * SC;

    // ---- slot mapping: lane's tracked channel; stage 3 = full-column dot ----
    const int t2 = (ql >> 2) & 1, t1 = (ql >> 1) & 1, t0 = ql & 1;
    const int vidx = t0 ? 4 : (t1 ? (t2 ? 3 : 2) : (t2 ? 1 : 0));
    // slot lanes per quarter: ch0<-0, ch1<-4, ch2<-2, ch3<-6, ch4<-1
    const bool wr = (ql == 0) | (ql == 1) | (ql == 2) | (ql == 4) | (ql == 6);
    const float b3v = b3[vidx];

    ull w3o[16];                         // W3 column vidx (packed over rows)
#pragma unroll
    for (int p = 0; p < 16; p++)
        w3o[p] = pack2(W3[(2 * p) * SDIM + vidx], W3[(2 * p + 1) * SDIM + vidx]);

    float stv = state0[b * SDIM + vidx]; // lane carries its slot's state channel

    const float* dptr = delta + (size_t)b * (TT * 3);
    float*       optr = out   + (size_t)b * (TT * SDIM) + vidx;

    float* line = &sh1[q][0];
    const ulonglong2* hp = (const ulonglong2*)line;

    // prefetch first delta chunk: lane (q,ql) holds step ql of batch b
    float r0 = dptr[ql * 3 + 0];
    float r1 = dptr[ql * 3 + 1];
    float r2 = dptr[ql * 3 + 2];

    for (int c = 0; c < NCHUNK; c++) {
        __syncwarp();                    // prior chunk's delta reads done
        *(float4*)(&shd[q][ql * 4]) = make_float4(r0, r1, r2, 0.f);
        __syncwarp();
        if (c + 1 < NCHUNK) {
            const float* np = dptr + (size_t)(c + 1) * (CHUNK * 3);
            r0 = np[ql * 3 + 0];
            r1 = np[ql * 3 + 1];
            r2 = np[ql * 3 + 2];
        }

#pragma unroll 2
        for (int tl = 0; tl < CHUNK; tl++) {
            const float4 dv = *(const float4*)(&shd[q][tl * 4]);

            // ---- broadcast state channels within the quarter (width=8 shfl) ----
            // shfl.sync also forms the convergence point that orders last step's
            // stage-3 LDS before this step's h1 STS (smem line reuse safety)
            const float s0 = SHF8(stv, 0);
            const float s1 = SHF8(stv, 4);
            const float s2 = SHF8(stv, 2);
            const float s3 = SHF8(stv, 6);
            const float s4 = SHF8(stv, 1);

            // ---- stage 1: packed f32x2 over channel pairs (16 fma2) ----
            const ull xd0 = dup2(dv.x);
            const ull xd1 = dup2(dv.y);
            const ull xd2 = dup2(dv.z);
            const ull xs0 = dup2(s0);
            const ull xs1 = dup2(s1);
            const ull xs2 = dup2(s2);
            const ull xs3 = dup2(s3);
            const ull xs4 = dup2(s4);

            ull acc01 = b1p01, acc23 = b1p23;
            fma2(acc01, xd0, w1p01[5]); fma2(acc23, xd0, w1p23[5]);
            fma2(acc01, xd1, w1p01[6]); fma2(acc23, xd1, w1p23[6]);
            fma2(acc01, xd2, w1p01[7]); fma2(acc23, xd2, w1p23[7]);
            fma2(acc01, xs0, w1p01[0]); fma2(acc23, xs0, w1p23[0]);
            fma2(acc01, xs1, w1p01[1]); fma2(acc23, xs1, w1p23[1]);
            fma2(acc01, xs2, w1p01[2]); fma2(acc23, xs2, w1p23[2]);
            fma2(acc01, xs3, w1p01[3]); fma2(acc23, xs3, w1p23[3]);
            fma2(acc01, xs4, w1p01[4]); fma2(acc23, xs4, w1p23[4]);

            float a0f, a1f, a2f, a3f;
            unpack2(acc01, a0f, a1f);
            unpack2(acc23, a2f, a3f);
            // 4 adjacent channels -> single STS.128
            *(float4*)(&line[jb]) = make_float4(tanh_hw(a0f), tanh_hw(a1f),
                                                tanh_hw(a2f), tanh_hw(a3f));
            __syncwarp();

            // ---- stage 2: 4 channels, 2 packed chains each (8 LDS.128 total) ----
            ull a0[4], a1[4];
            ulonglong2 u = hp[0];
#pragma unroll
            for (int cc = 0; cc < 4; cc++) {
                a0[cc] = mul2(u.x, w2c[cc][0]);
                a1[cc] = mul2(u.y, w2c[cc][1]);
            }
#pragma unroll
            for (int p = 1; p < 8; p++) {
                u = hp[p];
#pragma unroll
                for (int cc = 0; cc < 4; cc++) {
                    fma2(a0[cc], u.x, w2c[cc][2 * p]);
                    fma2(a1[cc], u.y, w2c[cc][2 * p + 1]);
                }
            }
            float h2v[4];
#pragma unroll
            for (int cc = 0; cc < 4; cc++)
                h2v[cc] = tanh_pre(sum2(add2(a0[cc], a1[cc])) + b2r[cc]);

            // ---- stage 3: publish h2 (reuse line: in-order STS after all LDS),
            //      then full-column dot for this lane's channel — NO shuffle tree
            *(float4*)(&line[jb]) = make_float4(h2v[0], h2v[1], h2v[2], h2v[3]);
            __syncwarp();

            ulonglong2 u2 = hp[0];
            ull o0 = mul2(u2.x, w3o[0]);
            ull o1 = mul2(u2.y, w3o[1]);
#pragma unroll
            for (int p = 1; p < 8; p++) {
                u2 = hp[p];
                fma2(o0, u2.x, w3o[2 * p]);
                fma2(o1, u2.y, w3o[2 * p + 1]);
            }
            stv += sum2(add2(o0, o1)) + b3v;   // every lane updates its channel

            if (wr) *optr = stv;         // lanes {0,4,2,6,1} -> channels {0..4}
            optr += SDIM;
        }
    }
}

extern "C" void kernel_launch(void* const* d_in, const int* in_sizes, int n_in,
                              void* d_out, int out_size)
{
    const float* delta  = (const float*)d_in[0];
    const float* state0 = (const float*)d_in[1];
    const float* W1     = (const float*)d_in[2];
    const float* b1     = (const float*)d_in[3];
    const float* W2     = (const float*)d_in[4];
    const float* b2     = (const float*)d_in[5];
    const float* W3     = (const float*)d_in[6];
    const float* b3     = (const float*)d_in[7];
    float* out = (float*)d_out;

    dim3 grid(NBATCH / 4);   // 1024 one-warp blocks, 4 batches each (8 lanes/batch)
    dim3 block(32);
    msc_seq_kernel<<<grid, block>>>(delta, state0, W1, b1, W2, b2, W3, b3, out);
}